// round 1
// baseline (speedup 1.0000x reference)
#include <cuda_runtime.h>
#include <math.h>

#define NHEADS 16
#define SEQ    2048
#define EMB    1024
#define NBATCH 2
#define DHEAD  64

// Scratch (allocation-free rule): device globals.
__device__ float g_q[NBATCH * NHEADS * SEQ * DHEAD];
__device__ float g_k[NBATCH * NHEADS * SEQ * DHEAD];
__device__ float g_v[NBATCH * NHEADS * SEQ * DHEAD];
__device__ float g_ctx[NBATCH * SEQ * EMB];

// ---------------------------------------------------------------------------
// NT GEMM: C[m,n] = sum_k A[m,k] * B[n,k]   (A: MxK row-major, B: NxK row-major)
// MODE 0: scatter into [B,H,S,D] layout (for Q/K/V projections)
// MODE 1: plain [M,N] with bias (output projection)
// Tile 128x128x8, 256 threads, 8x8 per thread.
// ---------------------------------------------------------------------------
template <int MODE>
__global__ __launch_bounds__(256) void gemm_nt(const float* __restrict__ A,
                                               const float* __restrict__ Bm,
                                               float* __restrict__ C,
                                               int M, int N, int K,
                                               const float* __restrict__ bias) {
    const int BM = 128, BN = 128, BK = 8;
    __shared__ float As[BK][BM];
    __shared__ float Bs[BK][BN];

    int tid = threadIdx.x;
    int tx = tid & 15;
    int ty = tid >> 4;
    int m0 = blockIdx.y * BM;
    int n0 = blockIdx.x * BN;

    float acc[8][8];
#pragma unroll
    for (int i = 0; i < 8; i++)
#pragma unroll
        for (int j = 0; j < 8; j++) acc[i][j] = 0.f;

    int lr = tid >> 1;        // 0..127
    int lc = (tid & 1) * 4;   // 0 or 4
    const float* Aptr = A + (size_t)(m0 + lr) * K + lc;
    const float* Bptr = Bm + (size_t)(n0 + lr) * K + lc;

    for (int k0 = 0; k0 < K; k0 += BK) {
        float4 av = *(const float4*)(Aptr + k0);
        float4 bv = *(const float4*)(Bptr + k0);
        As[lc + 0][lr] = av.x; As[lc + 1][lr] = av.y;
        As[lc + 2][lr] = av.z; As[lc + 3][lr] = av.w;
        Bs[lc + 0][lr] = bv.x; Bs[lc + 1][lr] = bv.y;
        Bs[lc + 2][lr] = bv.z; Bs[lc + 3][lr] = bv.w;
        __syncthreads();

#pragma unroll
        for (int kk = 0; kk < BK; kk++) {
            float a[8], b[8];
            *(float4*)&a[0] = *(const float4*)&As[kk][ty * 8];
            *(float4*)&a[4] = *(const float4*)&As[kk][ty * 8 + 4];
            *(float4*)&b[0] = *(const float4*)&Bs[kk][tx * 8];
            *(float4*)&b[4] = *(const float4*)&Bs[kk][tx * 8 + 4];
#pragma unroll
            for (int i = 0; i < 8; i++)
#pragma unroll
                for (int j = 0; j < 8; j++) acc[i][j] += a[i] * b[j];
        }
        __syncthreads();
    }

    if (MODE == 0) {
        // scatter into [B,H,S,D]: n -> (h = n/64, d = n%64); m -> (b = m/SEQ, s = m%SEQ)
#pragma unroll
        for (int i = 0; i < 8; i++) {
            int m = m0 + ty * 8 + i;
            int bb = m / SEQ;
            int ss = m % SEQ;
#pragma unroll
            for (int j4 = 0; j4 < 8; j4 += 4) {
                int n = n0 + tx * 8 + j4;
                int hh = n / DHEAD;
                int dd = n % DHEAD;
                float4 v = make_float4(acc[i][j4], acc[i][j4 + 1], acc[i][j4 + 2], acc[i][j4 + 3]);
                *(float4*)&C[(((size_t)bb * NHEADS + hh) * SEQ + ss) * DHEAD + dd] = v;
            }
        }
    } else {
        float bvals[8];
#pragma unroll
        for (int j = 0; j < 8; j++) bvals[j] = bias[n0 + tx * 8 + j];
#pragma unroll
        for (int i = 0; i < 8; i++) {
            int m = m0 + ty * 8 + i;
#pragma unroll
            for (int j4 = 0; j4 < 8; j4 += 4) {
                int n = n0 + tx * 8 + j4;
                float4 v = make_float4(acc[i][j4] + bvals[j4],
                                       acc[i][j4 + 1] + bvals[j4 + 1],
                                       acc[i][j4 + 2] + bvals[j4 + 2],
                                       acc[i][j4 + 3] + bvals[j4 + 3]);
                *(float4*)&C[(size_t)m * N + n] = v;
            }
        }
    }
}

// ---------------------------------------------------------------------------
// Causal flash attention, fp32. One block handles a 64-row Q tile of one (b,h).
// 256 threads = 16x16, 4x4 micro-tile. smem operands stored k-major (transposed)
// for conflict-free float4 loads. Writes ctx in [B,S,E] (= [B,S,H,D]) layout.
// ---------------------------------------------------------------------------
#define ALD 68  // padded leading dim for 64-wide smem tiles
#define ATTN_SMEM (4 * 64 * ALD * (int)sizeof(float))

__global__ __launch_bounds__(256) void attn_kernel(const float* __restrict__ Q,
                                                   const float* __restrict__ Kg,
                                                   const float* __restrict__ Vg,
                                                   float* __restrict__ ctx) {
    extern __shared__ float sm[];
    float* Qt = sm;               // Qt[d][r]
    float* Kt = Qt + 64 * ALD;    // Kt[d][c]
    float* Vs = Kt + 64 * ALD;    // Vs[c][d]
    float* Pt = Vs + 64 * ALD;    // Pt[c][r]

    int tid = threadIdx.x;
    int tx = tid & 15;
    int ty = tid >> 4;
    int qi = blockIdx.x;
    int h  = blockIdx.y;
    int b  = blockIdx.z;

    const float* qbase = Q + (((size_t)b * NHEADS + h) * SEQ + qi * 64) * DHEAD;
    const float* kbase0 = Kg + (((size_t)b * NHEADS + h) * SEQ) * DHEAD;
    const float* vbase0 = Vg + (((size_t)b * NHEADS + h) * SEQ) * DHEAD;

    // load Q tile transposed: Qt[d][r]
#pragma unroll
    for (int it = 0; it < 4; it++) {
        int idx = tid + it * 256;      // 0..1023
        int r = idx >> 4;              // 0..63
        int c4 = (idx & 15) * 4;       // 0..60
        float4 v = *(const float4*)(qbase + r * DHEAD + c4);
        Qt[(c4 + 0) * ALD + r] = v.x;
        Qt[(c4 + 1) * ALD + r] = v.y;
        Qt[(c4 + 2) * ALD + r] = v.z;
        Qt[(c4 + 3) * ALD + r] = v.w;
    }

    float m_i[4], l_i[4], o[4][4];
#pragma unroll
    for (int i = 0; i < 4; i++) {
        m_i[i] = -1e30f;
        l_i[i] = 0.f;
#pragma unroll
        for (int j = 0; j < 4; j++) o[i][j] = 0.f;
    }

    for (int jt = 0; jt <= qi; jt++) {
        __syncthreads();  // protect Kt/Vs/Pt (and Q load on first iter)
        const float* kbase = kbase0 + (size_t)jt * 64 * DHEAD;
        const float* vbase = vbase0 + (size_t)jt * 64 * DHEAD;
#pragma unroll
        for (int it = 0; it < 4; it++) {
            int idx = tid + it * 256;
            int r = idx >> 4;
            int c4 = (idx & 15) * 4;
            float4 kv = *(const float4*)(kbase + r * DHEAD + c4);
            Kt[(c4 + 0) * ALD + r] = kv.x;
            Kt[(c4 + 1) * ALD + r] = kv.y;
            Kt[(c4 + 2) * ALD + r] = kv.z;
            Kt[(c4 + 3) * ALD + r] = kv.w;
            float4 vv = *(const float4*)(vbase + r * DHEAD + c4);
            *(float4*)&Vs[r * ALD + c4] = vv;
        }
        __syncthreads();

        // S = (Q K^T) * 1/sqrt(D)
        float s[4][4];
#pragma unroll
        for (int i = 0; i < 4; i++)
#pragma unroll
            for (int j = 0; j < 4; j++) s[i][j] = 0.f;

#pragma unroll 8
        for (int k = 0; k < 64; k++) {
            float4 a = *(const float4*)&Qt[k * ALD + ty * 4];
            float4 bq = *(const float4*)&Kt[k * ALD + tx * 4];
            float av[4] = {a.x, a.y, a.z, a.w};
            float bv[4] = {bq.x, bq.y, bq.z, bq.w};
#pragma unroll
            for (int i = 0; i < 4; i++)
#pragma unroll
                for (int j = 0; j < 4; j++) s[i][j] += av[i] * bv[j];
        }

        const float scale = 0.125f;  // 1/sqrt(64)
#pragma unroll
        for (int i = 0; i < 4; i++)
#pragma unroll
            for (int j = 0; j < 4; j++) s[i][j] *= scale;

        if (jt == qi) {
#pragma unroll
            for (int i = 0; i < 4; i++)
#pragma unroll
                for (int j = 0; j < 4; j++)
                    if (tx * 4 + j > ty * 4 + i) s[i][j] = -1e30f;
        }

        // row max (reduce across the 16 lanes sharing ty; they are contiguous in the warp)
        float rmax[4];
#pragma unroll
        for (int i = 0; i < 4; i++) {
            float v = fmaxf(fmaxf(s[i][0], s[i][1]), fmaxf(s[i][2], s[i][3]));
#pragma unroll
            for (int msk = 1; msk < 16; msk <<= 1)
                v = fmaxf(v, __shfl_xor_sync(0xffffffffu, v, msk));
            rmax[i] = v;
        }

        float p[4][4], rsum[4];
#pragma unroll
        for (int i = 0; i < 4; i++) {
            float mnew = fmaxf(m_i[i], rmax[i]);
            float alpha = __expf(m_i[i] - mnew);
            float rs = 0.f;
#pragma unroll
            for (int j = 0; j < 4; j++) {
                p[i][j] = __expf(s[i][j] - mnew);
                rs += p[i][j];
            }
#pragma unroll
            for (int msk = 1; msk < 16; msk <<= 1)
                rs += __shfl_xor_sync(0xffffffffu, rs, msk);
            rsum[i] = rs;
            l_i[i] = l_i[i] * alpha + rsum[i];
            m_i[i] = mnew;
#pragma unroll
            for (int j = 0; j < 4; j++) o[i][j] *= alpha;
        }

        // store P transposed: Pt[c][r]
#pragma unroll
        for (int j = 0; j < 4; j++) {
            float4 v = make_float4(p[0][j], p[1][j], p[2][j], p[3][j]);
            *(float4*)&Pt[(tx * 4 + j) * ALD + ty * 4] = v;
        }
        __syncthreads();

        // O += P V
#pragma unroll 8
        for (int c = 0; c < 64; c++) {
            float4 pv = *(const float4*)&Pt[c * ALD + ty * 4];
            float4 vv = *(const float4*)&Vs[c * ALD + tx * 4];
            float pa[4] = {pv.x, pv.y, pv.z, pv.w};
            float va[4] = {vv.x, vv.y, vv.z, vv.w};
#pragma unroll
            for (int i = 0; i < 4; i++)
#pragma unroll
                for (int j = 0; j < 4; j++) o[i][j] += pa[i] * va[j];
        }
    }

    // write ctx in [B, S, H*D] layout
#pragma unroll
    for (int i = 0; i < 4; i++) {
        float inv = 1.f / l_i[i];
        int sg = qi * 64 + ty * 4 + i;
        float4 v = make_float4(o[i][0] * inv, o[i][1] * inv, o[i][2] * inv, o[i][3] * inv);
        *(float4*)&ctx[((size_t)b * SEQ + sg) * EMB + h * DHEAD + tx * 4] = v;
    }
}

// ---------------------------------------------------------------------------
extern "C" void kernel_launch(void* const* d_in, const int* in_sizes, int n_in,
                              void* d_out, int out_size) {
    const float* x  = (const float*)d_in[0];
    const float* Wk = (const float*)d_in[1];
    const float* Wq = (const float*)d_in[2];
    const float* Wv = (const float*)d_in[3];
    const float* Wu = (const float*)d_in[4];
    const float* bu = (const float*)d_in[5];
    float* out = (float*)d_out;

    float *qp, *kp, *vp, *cp;
    cudaGetSymbolAddress((void**)&qp, g_q);
    cudaGetSymbolAddress((void**)&kp, g_k);
    cudaGetSymbolAddress((void**)&vp, g_v);
    cudaGetSymbolAddress((void**)&cp, g_ctx);

    const int M = NBATCH * SEQ;  // 4096
    dim3 gg(EMB / 128, M / 128);

    gemm_nt<0><<<gg, 256>>>(x, Wq, qp, M, EMB, EMB, nullptr);
    gemm_nt<0><<<gg, 256>>>(x, Wk, kp, M, EMB, EMB, nullptr);
    gemm_nt<0><<<gg, 256>>>(x, Wv, vp, M, EMB, EMB, nullptr);

    cudaFuncSetAttribute(attn_kernel, cudaFuncAttributeMaxDynamicSharedMemorySize, ATTN_SMEM);
    attn_kernel<<<dim3(SEQ / 64, NHEADS, NBATCH), 256, ATTN_SMEM>>>(qp, kp, vp, cp);

    gemm_nt<1><<<gg, 256>>>(cp, Wu, out, M, EMB, EMB, bu);
}

// round 3
// speedup vs baseline: 1.5949x; 1.5949x over previous
#include <cuda_runtime.h>
#include <cstdint>
#include <math.h>

#define NHEADS 16
#define SEQ    2048
#define EMB    1024
#define NBATCH 2
#define DHEAD  64

// Scratch (allocation-free rule): device globals.
__device__ float g_q[NBATCH * NHEADS * SEQ * DHEAD];
__device__ float g_k[NBATCH * NHEADS * SEQ * DHEAD];
__device__ float g_v[NBATCH * NHEADS * SEQ * DHEAD];
__device__ float g_ctx[NBATCH * SEQ * EMB];

// ===========================================================================
// mma.sync m16n8k8 tf32 (family-common; maps to HMMA on sm_103)
// ===========================================================================
__device__ __forceinline__ uint32_t f2tf32(float f) {
    uint32_t u;
    asm("cvt.rna.tf32.f32 %0, %1;" : "=r"(u) : "f"(f));
    return u;
}
__device__ __forceinline__ void mma_tf32(float c[4], const uint32_t a[4], const uint32_t b[2]) {
    asm volatile(
        "mma.sync.aligned.m16n8k8.row.col.f32.tf32.tf32.f32 "
        "{%0,%1,%2,%3}, {%4,%5,%6,%7}, {%8,%9}, {%0,%1,%2,%3};"
        : "+f"(c[0]), "+f"(c[1]), "+f"(c[2]), "+f"(c[3])
        : "r"(a[0]), "r"(a[1]), "r"(a[2]), "r"(a[3]), "r"(b[0]), "r"(b[1]));
}

// ===========================================================================
// Tensor-core NT GEMM: C[m,n] = sum_k A[m,k]*B[n,k].  M=4096, N=1024, K=1024.
// CTA 128x128, 8 warps (warp tile 64x32), K-chunk 32, double-buffered smem
// holding PRE-PERMUTED tf32 fragments:
//   fragA[mt(8)][s(4)][reg(4)][lane(32)]   (16KB / stage)
//   fragB[nt(16)][s(4)][reg(2)][lane(32)]  (16KB / stage)
// STS: each thread's gmem float4 is contiguous in frag layout.
// LDS: 32-lane stride-1 b32 loads, conflict-free.
// MODE 0: scatter C into [B,H,S,D].  MODE 1: row-major + bias.
// ===========================================================================
#define GK        1024
#define KT        32
#define NKT       (GK / KT)
#define STAGE_FLT 8192                 // 4096 A + 4096 B floats
#define GEMM_SMEM (2 * STAGE_FLT * 4)  // 65536 B

template <int MODE>
__global__ __launch_bounds__(256) void gemm_tc(const float* __restrict__ A,
                                               const float* __restrict__ Bm,
                                               float* __restrict__ C,
                                               const float* __restrict__ bias) {
    extern __shared__ float smf[];
    const int tid = threadIdx.x;
    const int wid = tid >> 5;
    const int lane = tid & 31;
    const int m0 = blockIdx.y * 128;
    const int n0 = blockIdx.x * 128;

    // warp tile origin within CTA tile
    const int wm = (wid >> 2) * 64;   // 0 or 64
    const int wn = (wid & 3) * 32;    // 0,32,64,96

    // loader mapping: row r = tid>>1 (0..127), k window = (tid&1)*16
    const int lr = tid >> 1;
    const int lkb = (tid & 1) * 16;
    const float* Ap0 = A  + (size_t)(m0 + lr) * GK + lkb;
    const float* Bp0 = Bm + (size_t)(n0 + lr) * GK + lkb;

    // precompute frag STS offsets for the 4 float4s of A and B
    int offA[4], offB[4];
#pragma unroll
    for (int j = 0; j < 4; j++) {
        int k = lkb + j * 4;
        int s = k >> 3;
        int half = (k >> 2) & 1;
        {   // A: mt = lr>>4, rr = lr&15, g = rr&7, reg = (rr>>3) + half*2
            int mt = lr >> 4, rr = lr & 15, g = rr & 7;
            int reg = (rr >> 3) + half * 2;
            offA[j] = ((mt * 4 + s) * 4 + reg) * 32 + g * 4;
        }
        {   // B: nt = lr>>3, g = lr&7, reg = half
            int nt = lr >> 3, g = lr & 7;
            offB[j] = 4096 + ((nt * 4 + s) * 2 + half) * 32 + g * 4;
        }
    }

    float acc[4][4][4];  // [mt][nt][reg]
#pragma unroll
    for (int i = 0; i < 4; i++)
#pragma unroll
        for (int j = 0; j < 4; j++)
#pragma unroll
            for (int r = 0; r < 4; r++) acc[i][j][r] = 0.f;

    // ---- prologue: load chunk 0 ----
    {
        float* buf = smf;
#pragma unroll
        for (int j = 0; j < 4; j++) {
            float4 va = *(const float4*)(Ap0 + j * 4);
            float4 vb = *(const float4*)(Bp0 + j * 4);
            uint32_t ta[4] = {f2tf32(va.x), f2tf32(va.y), f2tf32(va.z), f2tf32(va.w)};
            uint32_t tb[4] = {f2tf32(vb.x), f2tf32(vb.y), f2tf32(vb.z), f2tf32(vb.w)};
            *(uint4*)&buf[offA[j]] = *(uint4*)ta;
            *(uint4*)&buf[offB[j]] = *(uint4*)tb;
        }
    }
    __syncthreads();

    const int mtg0 = wm >> 4;        // first m16 tile index of this warp
    const int ntg0 = wn >> 3;        // first n8 tile index

    for (int kt = 0; kt < NKT; kt++) {
        // prefetch next chunk into registers
        float4 pa[4], pb[4];
        if (kt + 1 < NKT) {
            const float* Ap = Ap0 + (kt + 1) * KT;
            const float* Bp = Bp0 + (kt + 1) * KT;
#pragma unroll
            for (int j = 0; j < 4; j++) {
                pa[j] = *(const float4*)(Ap + j * 4);
                pb[j] = *(const float4*)(Bp + j * 4);
            }
        }

        // compute from current buffer
        const float* buf = smf + (kt & 1) * STAGE_FLT;
#pragma unroll
        for (int s = 0; s < 4; s++) {
            uint32_t afr[4][4], bfr[4][2];
#pragma unroll
            for (int mt = 0; mt < 4; mt++) {
                const float* base = buf + ((mtg0 + mt) * 4 + s) * 4 * 32;
#pragma unroll
                for (int r = 0; r < 4; r++)
                    afr[mt][r] = __float_as_uint(base[r * 32 + lane]);
            }
#pragma unroll
            for (int nt = 0; nt < 4; nt++) {
                const float* base = buf + 4096 + ((ntg0 + nt) * 4 + s) * 2 * 32;
#pragma unroll
                for (int r = 0; r < 2; r++)
                    bfr[nt][r] = __float_as_uint(base[r * 32 + lane]);
            }
#pragma unroll
            for (int mt = 0; mt < 4; mt++)
#pragma unroll
                for (int nt = 0; nt < 4; nt++)
                    mma_tf32(acc[mt][nt], afr[mt], bfr[nt]);
        }

        // store next chunk
        if (kt + 1 < NKT) {
            float* nbuf = smf + ((kt + 1) & 1) * STAGE_FLT;
#pragma unroll
            for (int j = 0; j < 4; j++) {
                uint32_t ta[4] = {f2tf32(pa[j].x), f2tf32(pa[j].y), f2tf32(pa[j].z), f2tf32(pa[j].w)};
                uint32_t tb[4] = {f2tf32(pb[j].x), f2tf32(pb[j].y), f2tf32(pb[j].z), f2tf32(pb[j].w)};
                *(uint4*)&nbuf[offA[j]] = *(uint4*)ta;
                *(uint4*)&nbuf[offB[j]] = *(uint4*)tb;
            }
            __syncthreads();
        }
    }

    // ---- epilogue ----
    const int g = lane >> 2;          // groupID
    const int tg = lane & 3;          // thread-in-group
#pragma unroll
    for (int mt = 0; mt < 4; mt++) {
#pragma unroll
        for (int rh = 0; rh < 2; rh++) {   // row half: g or g+8
            const int m = m0 + wm + mt * 16 + g + rh * 8;
#pragma unroll
            for (int nt = 0; nt < 4; nt++) {
                const int n = n0 + wn + nt * 8 + tg * 2;
                float v0 = acc[mt][nt][rh * 2 + 0];
                float v1 = acc[mt][nt][rh * 2 + 1];
                if (MODE == 0) {
                    const int bb = m >> 11, ss = m & 2047;
                    const int hh = n >> 6,  dd = n & 63;
                    float* dst = C + (((size_t)bb * NHEADS + hh) * SEQ + ss) * DHEAD + dd;
                    *(float2*)dst = make_float2(v0, v1);
                } else {
                    float* dst = C + (size_t)m * EMB + n;
                    *(float2*)dst = make_float2(v0 + bias[n], v1 + bias[n + 1]);
                }
            }
        }
    }
}

// ---------------------------------------------------------------------------
// Causal flash attention, fp32 SIMT (unchanged from round 1).
// ---------------------------------------------------------------------------
#define ALD 68
#define ATTN_SMEM (4 * 64 * ALD * (int)sizeof(float))

__global__ __launch_bounds__(256) void attn_kernel(const float* __restrict__ Q,
                                                   const float* __restrict__ Kg,
                                                   const float* __restrict__ Vg,
                                                   float* __restrict__ ctx) {
    extern __shared__ float smf[];
    float* Qt = smf;
    float* Kt = Qt + 64 * ALD;
    float* Vs = Kt + 64 * ALD;
    float* Pt = Vs + 64 * ALD;

    int tid = threadIdx.x;
    int tx = tid & 15;
    int ty = tid >> 4;
    int qi = blockIdx.x;
    int h  = blockIdx.y;
    int b  = blockIdx.z;

    const float* qbase = Q + (((size_t)b * NHEADS + h) * SEQ + qi * 64) * DHEAD;
    const float* kbase0 = Kg + (((size_t)b * NHEADS + h) * SEQ) * DHEAD;
    const float* vbase0 = Vg + (((size_t)b * NHEADS + h) * SEQ) * DHEAD;

#pragma unroll
    for (int it = 0; it < 4; it++) {
        int idx = tid + it * 256;
        int r = idx >> 4;
        int c4 = (idx & 15) * 4;
        float4 v = *(const float4*)(qbase + r * DHEAD + c4);
        Qt[(c4 + 0) * ALD + r] = v.x;
        Qt[(c4 + 1) * ALD + r] = v.y;
        Qt[(c4 + 2) * ALD + r] = v.z;
        Qt[(c4 + 3) * ALD + r] = v.w;
    }

    float m_i[4], l_i[4], o[4][4];
#pragma unroll
    for (int i = 0; i < 4; i++) {
        m_i[i] = -1e30f;
        l_i[i] = 0.f;
#pragma unroll
        for (int j = 0; j < 4; j++) o[i][j] = 0.f;
    }

    for (int jt = 0; jt <= qi; jt++) {
        __syncthreads();
        const float* kbase = kbase0 + (size_t)jt * 64 * DHEAD;
        const float* vbase = vbase0 + (size_t)jt * 64 * DHEAD;
#pragma unroll
        for (int it = 0; it < 4; it++) {
            int idx = tid + it * 256;
            int r = idx >> 4;
            int c4 = (idx & 15) * 4;
            float4 kv = *(const float4*)(kbase + r * DHEAD + c4);
            Kt[(c4 + 0) * ALD + r] = kv.x;
            Kt[(c4 + 1) * ALD + r] = kv.y;
            Kt[(c4 + 2) * ALD + r] = kv.z;
            Kt[(c4 + 3) * ALD + r] = kv.w;
            float4 vv = *(const float4*)(vbase + r * DHEAD + c4);
            *(float4*)&Vs[r * ALD + c4] = vv;
        }
        __syncthreads();

        float s[4][4];
#pragma unroll
        for (int i = 0; i < 4; i++)
#pragma unroll
            for (int j = 0; j < 4; j++) s[i][j] = 0.f;

#pragma unroll 8
        for (int k = 0; k < 64; k++) {
            float4 a = *(const float4*)&Qt[k * ALD + ty * 4];
            float4 bq = *(const float4*)&Kt[k * ALD + tx * 4];
            float av[4] = {a.x, a.y, a.z, a.w};
            float bv[4] = {bq.x, bq.y, bq.z, bq.w};
#pragma unroll
            for (int i = 0; i < 4; i++)
#pragma unroll
                for (int j = 0; j < 4; j++) s[i][j] += av[i] * bv[j];
        }

        const float scale = 0.125f;
#pragma unroll
        for (int i = 0; i < 4; i++)
#pragma unroll
            for (int j = 0; j < 4; j++) s[i][j] *= scale;

        if (jt == qi) {
#pragma unroll
            for (int i = 0; i < 4; i++)
#pragma unroll
                for (int j = 0; j < 4; j++)
                    if (tx * 4 + j > ty * 4 + i) s[i][j] = -1e30f;
        }

        float rmax[4];
#pragma unroll
        for (int i = 0; i < 4; i++) {
            float v = fmaxf(fmaxf(s[i][0], s[i][1]), fmaxf(s[i][2], s[i][3]));
#pragma unroll
            for (int msk = 1; msk < 16; msk <<= 1)
                v = fmaxf(v, __shfl_xor_sync(0xffffffffu, v, msk));
            rmax[i] = v;
        }

        float p[4][4];
#pragma unroll
        for (int i = 0; i < 4; i++) {
            float mnew = fmaxf(m_i[i], rmax[i]);
            float alpha = __expf(m_i[i] - mnew);
            float rs = 0.f;
#pragma unroll
            for (int j = 0; j < 4; j++) {
                p[i][j] = __expf(s[i][j] - mnew);
                rs += p[i][j];
            }
#pragma unroll
            for (int msk = 1; msk < 16; msk <<= 1)
                rs += __shfl_xor_sync(0xffffffffu, rs, msk);
            l_i[i] = l_i[i] * alpha + rs;
            m_i[i] = mnew;
#pragma unroll
            for (int j = 0; j < 4; j++) o[i][j] *= alpha;
        }

#pragma unroll
        for (int j = 0; j < 4; j++) {
            float4 v = make_float4(p[0][j], p[1][j], p[2][j], p[3][j]);
            *(float4*)&Pt[(tx * 4 + j) * ALD + ty * 4] = v;
        }
        __syncthreads();

#pragma unroll 8
        for (int c = 0; c < 64; c++) {
            float4 pv = *(const float4*)&Pt[c * ALD + ty * 4];
            float4 vv = *(const float4*)&Vs[c * ALD + tx * 4];
            float pa[4] = {pv.x, pv.y, pv.z, pv.w};
            float va[4] = {vv.x, vv.y, vv.z, vv.w};
#pragma unroll
            for (int i = 0; i < 4; i++)
#pragma unroll
                for (int j = 0; j < 4; j++) o[i][j] += pa[i] * va[j];
        }
    }

#pragma unroll
    for (int i = 0; i < 4; i++) {
        float inv = 1.f / l_i[i];
        int sg = qi * 64 + ty * 4 + i;
        float4 v = make_float4(o[i][0] * inv, o[i][1] * inv, o[i][2] * inv, o[i][3] * inv);
        *(float4*)&ctx[((size_t)b * SEQ + sg) * EMB + h * DHEAD + tx * 4] = v;
    }
}

// ---------------------------------------------------------------------------
extern "C" void kernel_launch(void* const* d_in, const int* in_sizes, int n_in,
                              void* d_out, int out_size) {
    const float* x  = (const float*)d_in[0];
    const float* Wk = (const float*)d_in[1];
    const float* Wq = (const float*)d_in[2];
    const float* Wv = (const float*)d_in[3];
    const float* Wu = (const float*)d_in[4];
    const float* bu = (const float*)d_in[5];
    float* out = (float*)d_out;

    float *qp, *kp, *vp, *cp;
    cudaGetSymbolAddress((void**)&qp, g_q);
    cudaGetSymbolAddress((void**)&kp, g_k);
    cudaGetSymbolAddress((void**)&vp, g_v);
    cudaGetSymbolAddress((void**)&cp, g_ctx);

    cudaFuncSetAttribute(gemm_tc<0>, cudaFuncAttributeMaxDynamicSharedMemorySize, GEMM_SMEM);
    cudaFuncSetAttribute(gemm_tc<1>, cudaFuncAttributeMaxDynamicSharedMemorySize, GEMM_SMEM);
    cudaFuncSetAttribute(attn_kernel, cudaFuncAttributeMaxDynamicSharedMemorySize, ATTN_SMEM);

    dim3 gg(EMB / 128, (NBATCH * SEQ) / 128);  // (8, 32)

    gemm_tc<0><<<gg, 256, GEMM_SMEM>>>(x, Wq, qp, nullptr);
    gemm_tc<0><<<gg, 256, GEMM_SMEM>>>(x, Wk, kp, nullptr);
    gemm_tc<0><<<gg, 256, GEMM_SMEM>>>(x, Wv, vp, nullptr);

    attn_kernel<<<dim3(SEQ / 64, NHEADS, NBATCH), 256, ATTN_SMEM>>>(qp, kp, vp, cp);

    gemm_tc<1><<<gg, 256, GEMM_SMEM>>>(cp, Wu, out, bu);
}

// round 4
// speedup vs baseline: 2.9256x; 1.8344x over previous
#include <cuda_runtime.h>
#include <cstdint>
#include <math.h>

#define NHEADS 16
#define SEQ    2048
#define EMB    1024
#define NBATCH 2
#define DHEAD  64

// Scratch (allocation-free rule): device globals.
__device__ float g_q[NBATCH * NHEADS * SEQ * DHEAD];
__device__ float g_k[NBATCH * NHEADS * SEQ * DHEAD];
__device__ float g_v[NBATCH * NHEADS * SEQ * DHEAD];
__device__ float g_ctx[NBATCH * SEQ * EMB];

// ===========================================================================
// mma.sync m16n8k8 tf32 helpers (fragment maps validated by round-3 GEMM):
//   A(16x8): a0=A[g][tg]  a1=A[g+8][tg]  a2=A[g][tg+4]  a3=A[g+8][tg+4]
//   B(8x8):  b0=B[tg][g]  b1=B[tg+4][g]
//   C(16x8): c0=C[g][2tg] c1=C[g][2tg+1] c2=C[g+8][2tg] c3=C[g+8][2tg+1]
// ===========================================================================
__device__ __forceinline__ uint32_t f2tf32(float f) {
    uint32_t u;
    asm("cvt.rna.tf32.f32 %0, %1;" : "=r"(u) : "f"(f));
    return u;
}
__device__ __forceinline__ void mma_tf32(float c[4], const uint32_t a[4], const uint32_t b[2]) {
    asm volatile(
        "mma.sync.aligned.m16n8k8.row.col.f32.tf32.tf32.f32 "
        "{%0,%1,%2,%3}, {%4,%5,%6,%7}, {%8,%9}, {%0,%1,%2,%3};"
        : "+f"(c[0]), "+f"(c[1]), "+f"(c[2]), "+f"(c[3])
        : "r"(a[0]), "r"(a[1]), "r"(a[2]), "r"(a[3]), "r"(b[0]), "r"(b[1]));
}
__device__ __forceinline__ void cp16(uint32_t saddr, const void* gptr) {
    asm volatile("cp.async.cg.shared.global [%0], [%1], 16;" :: "r"(saddr), "l"(gptr));
}
#define CP_COMMIT() asm volatile("cp.async.commit_group;" ::: "memory")
#define CP_WAIT(n)  asm volatile("cp.async.wait_group %0;" :: "n"(n) : "memory")
__device__ __forceinline__ uint32_t smem_u32(const void* p) {
    uint32_t a;
    asm("{ .reg .u64 t; cvta.to.shared.u64 t, %1; cvt.u32.u64 %0, t; }" : "=r"(a) : "l"(p));
    return a;
}

// ===========================================================================
// Tensor-core NT GEMM (unchanged from round 3; validated).
// ===========================================================================
#define GK        1024
#define KT        32
#define NKT       (GK / KT)
#define STAGE_FLT 8192
#define GEMM_SMEM (2 * STAGE_FLT * 4)

template <int MODE>
__global__ __launch_bounds__(256) void gemm_tc(const float* __restrict__ A,
                                               const float* __restrict__ Bm,
                                               float* __restrict__ C,
                                               const float* __restrict__ bias) {
    extern __shared__ float smf[];
    const int tid = threadIdx.x;
    const int wid = tid >> 5;
    const int lane = tid & 31;
    const int m0 = blockIdx.y * 128;
    const int n0 = blockIdx.x * 128;
    const int wm = (wid >> 2) * 64;
    const int wn = (wid & 3) * 32;

    const int lr = tid >> 1;
    const int lkb = (tid & 1) * 16;
    const float* Ap0 = A  + (size_t)(m0 + lr) * GK + lkb;
    const float* Bp0 = Bm + (size_t)(n0 + lr) * GK + lkb;

    int offA[4], offB[4];
#pragma unroll
    for (int j = 0; j < 4; j++) {
        int k = lkb + j * 4;
        int s = k >> 3;
        int half = (k >> 2) & 1;
        {
            int mt = lr >> 4, rr = lr & 15, g = rr & 7;
            int reg = (rr >> 3) + half * 2;
            offA[j] = ((mt * 4 + s) * 4 + reg) * 32 + g * 4;
        }
        {
            int nt = lr >> 3, g = lr & 7;
            offB[j] = 4096 + ((nt * 4 + s) * 2 + half) * 32 + g * 4;
        }
    }

    float acc[4][4][4];
#pragma unroll
    for (int i = 0; i < 4; i++)
#pragma unroll
        for (int j = 0; j < 4; j++)
#pragma unroll
            for (int r = 0; r < 4; r++) acc[i][j][r] = 0.f;

    {
        float* buf = smf;
#pragma unroll
        for (int j = 0; j < 4; j++) {
            float4 va = *(const float4*)(Ap0 + j * 4);
            float4 vb = *(const float4*)(Bp0 + j * 4);
            uint32_t ta[4] = {f2tf32(va.x), f2tf32(va.y), f2tf32(va.z), f2tf32(va.w)};
            uint32_t tb[4] = {f2tf32(vb.x), f2tf32(vb.y), f2tf32(vb.z), f2tf32(vb.w)};
            *(uint4*)&buf[offA[j]] = *(uint4*)ta;
            *(uint4*)&buf[offB[j]] = *(uint4*)tb;
        }
    }
    __syncthreads();

    const int mtg0 = wm >> 4;
    const int ntg0 = wn >> 3;

    for (int kt = 0; kt < NKT; kt++) {
        float4 pa[4], pb[4];
        if (kt + 1 < NKT) {
            const float* Ap = Ap0 + (kt + 1) * KT;
            const float* Bp = Bp0 + (kt + 1) * KT;
#pragma unroll
            for (int j = 0; j < 4; j++) {
                pa[j] = *(const float4*)(Ap + j * 4);
                pb[j] = *(const float4*)(Bp + j * 4);
            }
        }

        const float* buf = smf + (kt & 1) * STAGE_FLT;
#pragma unroll
        for (int s = 0; s < 4; s++) {
            uint32_t afr[4][4], bfr[4][2];
#pragma unroll
            for (int mt = 0; mt < 4; mt++) {
                const float* base = buf + ((mtg0 + mt) * 4 + s) * 4 * 32;
#pragma unroll
                for (int r = 0; r < 4; r++)
                    afr[mt][r] = __float_as_uint(base[r * 32 + lane]);
            }
#pragma unroll
            for (int nt = 0; nt < 4; nt++) {
                const float* base = buf + 4096 + ((ntg0 + nt) * 4 + s) * 2 * 32;
#pragma unroll
                for (int r = 0; r < 2; r++)
                    bfr[nt][r] = __float_as_uint(base[r * 32 + lane]);
            }
#pragma unroll
            for (int mt = 0; mt < 4; mt++)
#pragma unroll
                for (int nt = 0; nt < 4; nt++)
                    mma_tf32(acc[mt][nt], afr[mt], bfr[nt]);
        }

        if (kt + 1 < NKT) {
            float* nbuf = smf + ((kt + 1) & 1) * STAGE_FLT;
#pragma unroll
            for (int j = 0; j < 4; j++) {
                uint32_t ta[4] = {f2tf32(pa[j].x), f2tf32(pa[j].y), f2tf32(pa[j].z), f2tf32(pa[j].w)};
                uint32_t tb[4] = {f2tf32(pb[j].x), f2tf32(pb[j].y), f2tf32(pb[j].z), f2tf32(pb[j].w)};
                *(uint4*)&nbuf[offA[j]] = *(uint4*)ta;
                *(uint4*)&nbuf[offB[j]] = *(uint4*)tb;
            }
            __syncthreads();
        }
    }

    const int g = lane >> 2;
    const int tg = lane & 3;
#pragma unroll
    for (int mt = 0; mt < 4; mt++) {
#pragma unroll
        for (int rh = 0; rh < 2; rh++) {
            const int m = m0 + wm + mt * 16 + g + rh * 8;
#pragma unroll
            for (int nt = 0; nt < 4; nt++) {
                const int n = n0 + wn + nt * 8 + tg * 2;
                float v0 = acc[mt][nt][rh * 2 + 0];
                float v1 = acc[mt][nt][rh * 2 + 1];
                if (MODE == 0) {
                    const int bb = m >> 11, ss = m & 2047;
                    const int hh = n >> 6,  dd = n & 63;
                    float* dst = C + (((size_t)bb * NHEADS + hh) * SEQ + ss) * DHEAD + dd;
                    *(float2*)dst = make_float2(v0, v1);
                } else {
                    float* dst = C + (size_t)m * EMB + n;
                    *(float2*)dst = make_float2(v0 + bias[n], v1 + bias[n + 1]);
                }
            }
        }
    }
}

// ===========================================================================
// Tensor-core causal flash attention.
// CTA = 128 Q rows, 8 warps x 16-row warp tile, KV tiles of 64, double-buffered
// cp.async. Q held in registers as A-fragments (pre-scaled by 1/sqrt(D)).
// K smem ld=68 (banks 4g+tg distinct), V smem ld=72 (banks 8tg+g distinct),
// per-warp P buffer ld=68.
// ===========================================================================
#define KLD 68
#define VLD 72
#define PLD 68
#define K_OFF(p) ((p) * (64 * KLD))
#define V_OFF(p) (2 * 64 * KLD + (p) * (64 * VLD))
#define P_OFF(w) (2 * 64 * KLD + 2 * 64 * VLD + (w) * (16 * PLD))
#define ATTN_SMEM ((2 * 64 * KLD + 2 * 64 * VLD + 8 * 16 * PLD) * 4)

__device__ __forceinline__ void attn_load_tile(uint32_t smbase, int tid, int buf,
                                               const float* kb, const float* vb) {
    uint32_t kdst = smbase + K_OFF(buf) * 4;
    uint32_t vdst = smbase + V_OFF(buf) * 4;
#pragma unroll
    for (int it = 0; it < 4; it++) {
        int id = tid + it * 256;
        int r = id >> 4;
        int c4 = (id & 15) * 4;
        cp16(kdst + (r * KLD + c4) * 4, kb + r * DHEAD + c4);
        cp16(vdst + (r * VLD + c4) * 4, vb + r * DHEAD + c4);
    }
    CP_COMMIT();
}

__global__ __launch_bounds__(256, 2) void attn_tc(const float* __restrict__ Q,
                                                  const float* __restrict__ Kg,
                                                  const float* __restrict__ Vg,
                                                  float* __restrict__ ctx) {
    extern __shared__ float smf[];
    const uint32_t smbase = smem_u32(smf);
    const int tid  = threadIdx.x;
    const int wid  = tid >> 5;
    const int lane = tid & 31;
    const int g    = lane >> 2;
    const int tg   = lane & 3;
    const int blkE = gridDim.x - 1 - blockIdx.x;   // heavy blocks first
    const int h = blockIdx.y;
    const int b = blockIdx.z;
    const int wrow = blkE * 128 + wid * 16;        // warp's first Q row

    const float* qb  = Q  + (((size_t)b * NHEADS + h) * SEQ + wrow) * DHEAD;
    const float* kb0 = Kg + (((size_t)b * NHEADS + h) * SEQ) * DHEAD;
    const float* vb0 = Vg + (((size_t)b * NHEADS + h) * SEQ) * DHEAD;

    // Q A-fragments, pre-scaled by 1/sqrt(D)
    uint32_t qf[8][4];
#pragma unroll
    for (int kk = 0; kk < 8; kk++) {
        qf[kk][0] = f2tf32(0.125f * qb[(size_t)g * DHEAD + kk * 8 + tg]);
        qf[kk][1] = f2tf32(0.125f * qb[(size_t)(g + 8) * DHEAD + kk * 8 + tg]);
        qf[kk][2] = f2tf32(0.125f * qb[(size_t)g * DHEAD + kk * 8 + tg + 4]);
        qf[kk][3] = f2tf32(0.125f * qb[(size_t)(g + 8) * DHEAD + kk * 8 + tg + 4]);
    }

    float oacc[8][4];
#pragma unroll
    for (int nt = 0; nt < 8; nt++)
#pragma unroll
        for (int r = 0; r < 4; r++) oacc[nt][r] = 0.f;
    float m_[2] = {-1e30f, -1e30f};
    float l_[2] = {0.f, 0.f};

    const int nT = 2 * blkE + 2;
    attn_load_tile(smbase, tid, 0, kb0, vb0);

    for (int jt = 0; jt < nT; jt++) {
        const int p = jt & 1;
        if (jt + 1 < nT) {
            attn_load_tile(smbase, tid, 1 - p,
                           kb0 + (size_t)(jt + 1) * 64 * DHEAD,
                           vb0 + (size_t)(jt + 1) * 64 * DHEAD);
            CP_WAIT(1);
        } else {
            CP_WAIT(0);
        }
        __syncthreads();

        if (jt * 64 <= wrow + 15) {   // any column visible for this warp
            const float* Ks = smf + K_OFF(p);
            const float* Vs = smf + V_OFF(p);
            float* Ps = smf + P_OFF(wid);

            // ---- S = Q K^T (scaled) ----
            float sacc[8][4];
#pragma unroll
            for (int nt = 0; nt < 8; nt++)
#pragma unroll
                for (int r = 0; r < 4; r++) sacc[nt][r] = 0.f;

#pragma unroll
            for (int nt = 0; nt < 8; nt++) {
                const float* krow = Ks + (nt * 8 + g) * KLD;
#pragma unroll
                for (int kk = 0; kk < 8; kk++) {
                    uint32_t bb[2];
                    bb[0] = __float_as_uint(krow[kk * 8 + tg]);
                    bb[1] = __float_as_uint(krow[kk * 8 + tg + 4]);
                    mma_tf32(sacc[nt], qf[kk], bb);
                }
            }

            // ---- causal mask (diagonal tiles only) ----
            if (jt * 64 + 63 > wrow) {
#pragma unroll
                for (int nt = 0; nt < 8; nt++) {
                    int colb = jt * 64 + nt * 8 + 2 * tg;
#pragma unroll
                    for (int rh = 0; rh < 2; rh++) {
                        int row = wrow + g + 8 * rh;
                        if (colb > row)     sacc[nt][rh * 2 + 0] = -1e30f;
                        if (colb + 1 > row) sacc[nt][rh * 2 + 1] = -1e30f;
                    }
                }
            }

            // ---- online softmax ----
            float rmax[2] = {-1e30f, -1e30f};
#pragma unroll
            for (int nt = 0; nt < 8; nt++) {
#pragma unroll
                for (int rh = 0; rh < 2; rh++)
                    rmax[rh] = fmaxf(rmax[rh],
                                     fmaxf(sacc[nt][rh * 2], sacc[nt][rh * 2 + 1]));
            }
#pragma unroll
            for (int rh = 0; rh < 2; rh++) {
                rmax[rh] = fmaxf(rmax[rh], __shfl_xor_sync(0xffffffffu, rmax[rh], 1));
                rmax[rh] = fmaxf(rmax[rh], __shfl_xor_sync(0xffffffffu, rmax[rh], 2));
            }
            float alpha[2], rsum[2] = {0.f, 0.f};
#pragma unroll
            for (int rh = 0; rh < 2; rh++) {
                float mnew = fmaxf(m_[rh], rmax[rh]);
                alpha[rh] = __expf(m_[rh] - mnew);
                m_[rh] = mnew;
            }
#pragma unroll
            for (int nt = 0; nt < 8; nt++) {
#pragma unroll
                for (int rh = 0; rh < 2; rh++) {
                    float p0 = __expf(sacc[nt][rh * 2 + 0] - m_[rh]);
                    float p1 = __expf(sacc[nt][rh * 2 + 1] - m_[rh]);
                    sacc[nt][rh * 2 + 0] = p0;
                    sacc[nt][rh * 2 + 1] = p1;
                    rsum[rh] += p0 + p1;
                }
            }
#pragma unroll
            for (int rh = 0; rh < 2; rh++) {
                rsum[rh] += __shfl_xor_sync(0xffffffffu, rsum[rh], 1);
                rsum[rh] += __shfl_xor_sync(0xffffffffu, rsum[rh], 2);
                l_[rh] = l_[rh] * alpha[rh] + rsum[rh];
            }
#pragma unroll
            for (int nt = 0; nt < 8; nt++) {
#pragma unroll
                for (int rh = 0; rh < 2; rh++) {
                    oacc[nt][rh * 2 + 0] *= alpha[rh];
                    oacc[nt][rh * 2 + 1] *= alpha[rh];
                }
            }

            // ---- P -> per-warp smem (tf32 bits) ----
#pragma unroll
            for (int nt = 0; nt < 8; nt++) {
                uint2 u0 = make_uint2(f2tf32(sacc[nt][0]), f2tf32(sacc[nt][1]));
                uint2 u1 = make_uint2(f2tf32(sacc[nt][2]), f2tf32(sacc[nt][3]));
                *(uint2*)&Ps[g * PLD + nt * 8 + 2 * tg] = u0;
                *(uint2*)&Ps[(g + 8) * PLD + nt * 8 + 2 * tg] = u1;
            }
            __syncwarp();

            // ---- O += P V ----
#pragma unroll
            for (int kkc = 0; kkc < 8; kkc++) {
                uint32_t a[4];
                a[0] = __float_as_uint(Ps[g * PLD + kkc * 8 + tg]);
                a[1] = __float_as_uint(Ps[(g + 8) * PLD + kkc * 8 + tg]);
                a[2] = __float_as_uint(Ps[g * PLD + kkc * 8 + tg + 4]);
                a[3] = __float_as_uint(Ps[(g + 8) * PLD + kkc * 8 + tg + 4]);
                const float* v0 = Vs + (kkc * 8 + tg) * VLD;
                const float* v1 = Vs + (kkc * 8 + tg + 4) * VLD;
#pragma unroll
                for (int ntd = 0; ntd < 8; ntd++) {
                    uint32_t bb[2];
                    bb[0] = __float_as_uint(v0[ntd * 8 + g]);
                    bb[1] = __float_as_uint(v1[ntd * 8 + g]);
                    mma_tf32(oacc[ntd], a, bb);
                }
            }
        }
        __syncthreads();
    }

    // ---- epilogue: O / l -> ctx [B,S,E] ----
    float inv[2] = {1.f / l_[0], 1.f / l_[1]};
#pragma unroll
    for (int rh = 0; rh < 2; rh++) {
        const int r = wrow + g + 8 * rh;
        float* dst = ctx + ((size_t)b * SEQ + r) * EMB + h * DHEAD + 2 * tg;
#pragma unroll
        for (int nt = 0; nt < 8; nt++) {
            float2 v = make_float2(oacc[nt][rh * 2 + 0] * inv[rh],
                                   oacc[nt][rh * 2 + 1] * inv[rh]);
            *(float2*)(dst + nt * 8) = v;
        }
    }
}

// ---------------------------------------------------------------------------
extern "C" void kernel_launch(void* const* d_in, const int* in_sizes, int n_in,
                              void* d_out, int out_size) {
    const float* x  = (const float*)d_in[0];
    const float* Wk = (const float*)d_in[1];
    const float* Wq = (const float*)d_in[2];
    const float* Wv = (const float*)d_in[3];
    const float* Wu = (const float*)d_in[4];
    const float* bu = (const float*)d_in[5];
    float* out = (float*)d_out;

    float *qp, *kp, *vp, *cp;
    cudaGetSymbolAddress((void**)&qp, g_q);
    cudaGetSymbolAddress((void**)&kp, g_k);
    cudaGetSymbolAddress((void**)&vp, g_v);
    cudaGetSymbolAddress((void**)&cp, g_ctx);

    cudaFuncSetAttribute(gemm_tc<0>, cudaFuncAttributeMaxDynamicSharedMemorySize, GEMM_SMEM);
    cudaFuncSetAttribute(gemm_tc<1>, cudaFuncAttributeMaxDynamicSharedMemorySize, GEMM_SMEM);
    cudaFuncSetAttribute(attn_tc, cudaFuncAttributeMaxDynamicSharedMemorySize, ATTN_SMEM);

    dim3 gg(EMB / 128, (NBATCH * SEQ) / 128);  // (8, 32)

    gemm_tc<0><<<gg, 256, GEMM_SMEM>>>(x, Wq, qp, nullptr);
    gemm_tc<0><<<gg, 256, GEMM_SMEM>>>(x, Wk, kp, nullptr);
    gemm_tc<0><<<gg, 256, GEMM_SMEM>>>(x, Wv, vp, nullptr);

    attn_tc<<<dim3(SEQ / 128, NHEADS, NBATCH), 256, ATTN_SMEM>>>(qp, kp, vp, cp);

    gemm_tc<1><<<gg, 256, GEMM_SMEM>>>(cp, Wu, out, bu);
}